// round 4
// baseline (speedup 1.0000x reference)
#include <cuda_runtime.h>

// ---------------- problem constants ----------------
#define B_     64
#define CIN    32
#define COUT   16
#define HH     64
#define WW     64
#define S_     4096          // 64*64 output locations
#define KK     288           // CIN * 3 * 3

// patch [KK][B_] + weight [KK][COUT]  (floats)
#define SMEM_FLOATS (KK * B_ + KK * COUT)
#define SMEM_BYTES  (SMEM_FLOATS * 4)    // 92160

// Scratch: X transposed to [ih][iw][cin][b]  (33.55 MB) — static device global, no alloc.
__device__ float g_Xt[(size_t)HH * WW * CIN * B_];

// ---------------------------------------------------------------------------
// Pre-pass: X[b][cin][ih][iw]  ->  Xt[ih][iw][cin][b]
// One CTA per (cin, ih) slab: a 64(b) x 64(iw) transpose through padded SMEM.
// Both global read and write are fully coalesced (128B per warp).
// ---------------------------------------------------------------------------
__global__ void __launch_bounds__(256) transpose_kernel(const float* __restrict__ X) {
    __shared__ float tile[64][65];
    const int cin = blockIdx.x >> 6;   // 0..31
    const int ih  = blockIdx.x & 63;   // 0..63
    const int t   = threadIdx.x;       // 0..255

    // ---- load: consecutive lanes -> consecutive iw (coalesced) ----
    {
        const int iw  = t & 63;
        const int bg  = t >> 6;                       // 0..3
        const float* src = X + (size_t)cin * (HH * WW) + (size_t)ih * WW;
        #pragma unroll
        for (int r = 0; r < 16; ++r) {
            const int b = bg * 16 + r;
            tile[iw][b] = src[(size_t)b * (CIN * HH * WW) + iw];
        }
    }
    __syncthreads();
    // ---- store: consecutive lanes -> consecutive b (coalesced) ----
    {
        const int b  = t & 63;
        const int wg = t >> 6;                        // 0..3
        float* dst = g_Xt + ((size_t)ih * WW) * (CIN * B_) + (size_t)cin * B_;
        #pragma unroll
        for (int r = 0; r < 16; ++r) {
            const int iw = wg * 16 + r;
            dst[(size_t)iw * (CIN * B_) + b] = tile[iw][b];
        }
    }
}

// ---------------------------------------------------------------------------
// Main kernel: one CTA per output location s = oh*64+ow.
//   SMEM patch[k][b]  (k = cin*9 + i*3 + j), with bias_s pre-added to every
//   element (out-of-bounds taps become exactly bias_s, matching unfold+bias).
//   SMEM weight[k][c] copied straight from weight[s].
//   Thread (b = tid>>2, cg = tid&3) accumulates 4 c-outputs as 2 packed f32x2.
// ---------------------------------------------------------------------------
__global__ void __launch_bounds__(256) lc_kernel(const float* __restrict__ Wt,
                                                 const float* __restrict__ bias,
                                                 float* __restrict__ out) {
    extern __shared__ float sm[];
    float* sp = sm;                 // patch: [KK][B_]
    float* sw = sm + KK * B_;       // weight: [KK][COUT]

    const int s   = blockIdx.x;
    const int oh  = s >> 6;
    const int ow  = s & 63;
    const int tid = threadIdx.x;
    const float bs = bias[s];

    // ---- stage per-location weight (4608 floats, contiguous) ----
    {
        const float4* gw  = (const float4*)(Wt + (size_t)s * (KK * COUT));
        float4*       sw4 = (float4*)sw;
        #pragma unroll
        for (int t = tid; t < (KK * COUT) / 4; t += 256) sw4[t] = gw[t];
    }

    // ---- stage patch: 9 taps, each a contiguous [cin][b] 8KB block of Xt ----
    #pragma unroll
    for (int ij = 0; ij < 9; ++ij) {
        const int ih = oh + ij / 3 - 1;
        const int iw = ow + ij % 3 - 1;
        const bool valid = ((unsigned)ih < (unsigned)HH) && ((unsigned)iw < (unsigned)WW);
        const size_t off = valid ? (size_t)(ih * WW + iw) * (CIN * B_) : 0;
        const float4* src = (const float4*)(g_Xt + off);
        #pragma unroll
        for (int t = tid; t < (CIN * B_) / 4; t += 256) {   // 512 float4
            float4 v = valid ? src[t] : make_float4(0.f, 0.f, 0.f, 0.f);
            v.x += bs; v.y += bs; v.z += bs; v.w += bs;
            const int cin = t >> 4;          // (t*4)/64
            const int bq  = t & 15;          // float4 index within the b-row
            ((float4*)(sp + (size_t)(cin * 9 + ij) * B_))[bq] = v;
        }
    }
    __syncthreads();

    // ---- mainloop: 288 k-steps, 4 outputs/thread via packed f32x2 FMA ----
    const int b  = tid >> 2;     // 0..63
    const int cg = tid & 3;      // c base = cg*4

    const float* pb = sp + b;                                  // stride B_ per k
    const ulonglong2* wv = ((const ulonglong2*)sw) + cg;       // stride 4 per k (16B units)

    unsigned long long acc0 = 0ull, acc1 = 0ull;               // {c0,c1},{c2,c3}

    #pragma unroll 8
    for (int k = 0; k < KK; ++k) {
        const float a = pb[(size_t)k * B_];
        unsigned long long a2;
        asm("mov.b64 %0, {%1, %1};" : "=l"(a2) : "f"(a));      // splat
        const ulonglong2 w = wv[(size_t)k * (COUT / 4)];       // ld.shared.v2.u64
        asm("fma.rn.f32x2 %0, %1, %2, %0;" : "+l"(acc0) : "l"(a2), "l"(w.x));
        asm("fma.rn.f32x2 %0, %1, %2, %0;" : "+l"(acc1) : "l"(a2), "l"(w.y));
    }

    float c0, c1, c2, c3;
    asm("mov.b64 {%0, %1}, %2;" : "=f"(c0), "=f"(c1) : "l"(acc0));
    asm("mov.b64 {%0, %1}, %2;" : "=f"(c2), "=f"(c3) : "l"(acc1));

    // out[b][c][s], c = cg*4 .. cg*4+3
    float* o = out + ((size_t)b * COUT + cg * 4) * S_ + s;
    o[0]      = c0;
    o[S_]     = c1;
    o[2 * S_] = c2;
    o[3 * S_] = c3;
}

// ---------------------------------------------------------------------------
extern "C" void kernel_launch(void* const* d_in, const int* in_sizes, int n_in,
                              void* d_out, int out_size) {
    // Identify inputs by element count (robust to ordering).
    const float* X  = nullptr;   // 64*32*64*64  = 8388608
    const float* Wt = nullptr;   // 4096*288*16  = 18874368
    const float* Bp = nullptr;   // 4096
    for (int i = 0; i < n_in; ++i) {
        if      (in_sizes[i] == B_ * CIN * HH * WW) X  = (const float*)d_in[i];
        else if (in_sizes[i] == S_ * KK * COUT)     Wt = (const float*)d_in[i];
        else if (in_sizes[i] == S_)                 Bp = (const float*)d_in[i];
    }

    // Opt in to >48KB dynamic SMEM (idempotent host-side attribute, capture-safe).
    cudaFuncSetAttribute(lc_kernel, cudaFuncAttributeMaxDynamicSharedMemorySize, SMEM_BYTES);

    transpose_kernel<<<CIN * HH, 256>>>(X);
    lc_kernel<<<S_, 256, SMEM_BYTES>>>(Wt, Bp, (float*)d_out);
}

// round 7
// speedup vs baseline: 1.1227x; 1.1227x over previous
#include <cuda_runtime.h>

// ---------------- problem constants ----------------
#define B_     64
#define CIN    32
#define COUT   16
#define HH     64
#define WW     64
#define S_     4096          // 64*64 output locations
#define KK     288           // CIN * 3 * 3

// ---- lc kernel tiling ----
#define SLICES 16            // k-split factor
#define KSL    (KK / SLICES) // 18 k-steps per slice
#define PROW   68            // patch row pitch in floats (272B: 256B data + swizzle pad)
#define WROW   20            // weight row pitch in floats (80B: 64B data + pad)

#define SP_FLOATS (KK * PROW)              // 19584
#define SW_FLOATS (KK * WROW)              // 5760
#define SMEM_FLOATS (SP_FLOATS + SW_FLOATS)
#define SMEM_BYTES  (SMEM_FLOATS * 4)      // 101376  -> 2 CTAs/SM

// partial-sum layout (reuses patch region): part[c][bp][slice], u64 units
#define PART_BP_STRIDE 17                  // 17 u64 (odd -> bank spread)
#define PART_C_STRIDE  (33 * 17)           // 561 u64 (== 1 mod 16 -> bank spread)

// Scratch: X transposed to [ih][iw][cin][b]  (33.55 MB) — static device global.
__device__ float g_Xt[(size_t)HH * WW * CIN * B_];

// ---------------- tiny f32x2 helpers ----------------
__device__ __forceinline__ void fma2(unsigned long long& d,
                                     unsigned long long a, unsigned long long b) {
    asm("fma.rn.f32x2 %0, %1, %2, %0;" : "+l"(d) : "l"(a), "l"(b));
}
__device__ __forceinline__ unsigned long long splat2(float x) {
    unsigned long long r;
    asm("mov.b64 %0, {%1, %1};" : "=l"(r) : "f"(x));
    return r;
}
__device__ __forceinline__ unsigned long long add2(unsigned long long a,
                                                   unsigned long long b) {
    unsigned long long r;
    asm("add.rn.f32x2 %0, %1, %2;" : "=l"(r) : "l"(a), "l"(b));
    return r;
}

// ---------------------------------------------------------------------------
// Pre-pass: X[b][cin][ih][iw] -> Xt[ih][iw][cin][b]  (coalesced both sides)
// ---------------------------------------------------------------------------
__global__ void __launch_bounds__(256) transpose_kernel(const float* __restrict__ X) {
    __shared__ float tile[64][65];
    const int cin = blockIdx.x >> 6;
    const int ih  = blockIdx.x & 63;
    const int t   = threadIdx.x;
    {
        const int iw = t & 63;
        const int bg = t >> 6;
        const float* src = X + (size_t)cin * (HH * WW) + (size_t)ih * WW;
        #pragma unroll
        for (int r = 0; r < 16; ++r) {
            const int b = bg * 16 + r;
            tile[iw][b] = src[(size_t)b * (CIN * HH * WW) + iw];
        }
    }
    __syncthreads();
    {
        const int b  = t & 63;
        const int wg = t >> 6;
        float* dst = g_Xt + ((size_t)ih * WW) * (CIN * B_) + (size_t)cin * B_;
        #pragma unroll
        for (int r = 0; r < 16; ++r) {
            const int iw = wg * 16 + r;
            dst[(size_t)iw * (CIN * B_) + b] = tile[iw][b];
        }
    }
}

// ---------------------------------------------------------------------------
// Main kernel: one CTA per location s. 256 threads = 16 k-slices x (8 bg x 2 cg).
// Thread computes an 8b x 8c tile over its 18 k-steps via packed f32x2 FMA,
// then a 16-way smem reduction combines the k-slices.
// ---------------------------------------------------------------------------
__global__ void __launch_bounds__(256, 2) lc_kernel(const float* __restrict__ Wt,
                                                    const float* __restrict__ bias,
                                                    float* __restrict__ out) {
    extern __shared__ float sm[];
    float* sp = sm;                    // patch: [KK][PROW] floats, swizzled chunks
    float* sw = sm + SP_FLOATS;        // weight: [KK][WROW] floats

    const int s   = blockIdx.x;
    const int oh  = s >> 6;
    const int ow  = s & 63;
    const int tid = threadIdx.x;
    const float bs = bias[s];

    // ---- stage per-location weight: 288 rows x 16 floats into pitch-20 rows ----
    {
        const float4* gw = (const float4*)(Wt + (size_t)s * (KK * COUT));
        #pragma unroll
        for (int t = tid; t < (KK * COUT) / 4; t += 256) {   // 1152 float4
            const int k = t >> 2;
            const int q = t & 3;
            ((float4*)(sw + k * WROW))[q] = gw[t];
        }
    }

    // ---- stage patch: 9 taps, each a contiguous [cin][b] 8KB block of Xt.
    //      bias pre-added; OOB taps become exactly bias (matches unfold+bias).
    //      Rows pitch PROW with XOR-16B chunk swizzle: 32B chunk c lives at
    //      byte c*32 + ((c&4)?16:0). float4 q (0..15) -> slot q + (q>>3). ----
    #pragma unroll
    for (int ij = 0; ij < 9; ++ij) {
        const int ih = oh + ij / 3 - 1;
        const int iw = ow + ij % 3 - 1;
        const bool valid = ((unsigned)ih < (unsigned)HH) && ((unsigned)iw < (unsigned)WW);
        const size_t off = valid ? (size_t)(ih * WW + iw) * (CIN * B_) : 0;
        const float4* src = (const float4*)(g_Xt + off);
        #pragma unroll
        for (int t = tid; t < (CIN * B_) / 4; t += 256) {    // 512 float4
            float4 v = valid ? src[t] : make_float4(0.f, 0.f, 0.f, 0.f);
            v.x += bs; v.y += bs; v.z += bs; v.w += bs;
            const int cin = t >> 4;
            const int q   = t & 15;
            const int swq = q + ((q >> 3) & 1);              // swizzled float4 slot
            ((float4*)(sp + (size_t)(cin * 9 + ij) * PROW))[swq] = v;
        }
    }
    __syncthreads();

    // ---- mainloop ----
    const int slice = tid >> 4;          // 0..15
    const int idx   = tid & 15;
    const int bg    = idx >> 1;          // 0..7  -> b base = bg*8
    const int cg    = idx & 1;           // 0..1  -> c base = cg*8
    const int kbase = slice * KSL;

    // swizzled byte offset of 32B chunk bg within a patch row
    const int pch_off = bg * 32 + ((bg & 4) << 2);

    const char* prow = (const char*)sp + (size_t)kbase * (PROW * 4) + pch_off;
    const char* wrow = (const char*)sw + (size_t)kbase * (WROW * 4) + cg * 32;

    unsigned long long acc[4][8];
    #pragma unroll
    for (int i = 0; i < 4; ++i)
        #pragma unroll
        for (int j = 0; j < 8; ++j) acc[i][j] = 0ull;

    #pragma unroll 3
    for (int k = 0; k < KSL; ++k) {
        // patch: 8 b-values = 4 packed f32x2 (two LDS.128)
        const ulonglong2 u0 = *(const ulonglong2*)(prow + (size_t)k * (PROW * 4));
        const ulonglong2 u1 = *(const ulonglong2*)(prow + (size_t)k * (PROW * 4) + 16);
        // weight: 8 c-values (two LDS.128)
        const float4 w01 = *(const float4*)(wrow + (size_t)k * (WROW * 4));
        const float4 w23 = *(const float4*)(wrow + (size_t)k * (WROW * 4) + 16);

        const unsigned long long p[4] = { u0.x, u0.y, u1.x, u1.y };
        const unsigned long long w2[8] = {
            splat2(w01.x), splat2(w01.y), splat2(w01.z), splat2(w01.w),
            splat2(w23.x), splat2(w23.y), splat2(w23.z), splat2(w23.w)
        };
        #pragma unroll
        for (int i = 0; i < 4; ++i)
            #pragma unroll
            for (int j = 0; j < 8; ++j)
                fma2(acc[i][j], p[i], w2[j]);
    }

    // ---- k-slice reduction through smem (reuses patch region) ----
    __syncthreads();   // everyone done reading sp/sw

    unsigned long long* part = (unsigned long long*)sm;  // part[c][bp][slice]
    const int c0  = cg * 8;
    const int bp0 = bg * 4;
    #pragma unroll
    for (int ii = 0; ii < 4; ++ii) {
        const int i  = (ii + bg) & 3;       // bank rotation across bg lanes
        const int bp = bp0 + i;
        #pragma unroll
        for (int j = 0; j < 8; ++j)
            part[(size_t)(c0 + j) * PART_C_STRIDE + bp * PART_BP_STRIDE + slice] = acc[i][j];
    }
    __syncthreads();

    // 512 (c,bp) entries, 2 per thread: sum 16 slices, write out[b][c][s]
    #pragma unroll
    for (int e = tid; e < 512; e += 256) {
        const int c  = e >> 5;
        const int bp = e & 31;
        const unsigned long long* base =
            part + (size_t)c * PART_C_STRIDE + bp * PART_BP_STRIDE;
        unsigned long long sum = base[0];
        #pragma unroll
        for (int t = 1; t < SLICES; ++t) sum = add2(sum, base[t]);
        float lo, hi;
        asm("mov.b64 {%0, %1}, %2;" : "=f"(lo), "=f"(hi) : "l"(sum));
        out[((size_t)(2 * bp)     * COUT + c) * S_ + s] = lo;
        out[((size_t)(2 * bp + 1) * COUT + c) * S_ + s] = hi;
    }
}

// ---------------------------------------------------------------------------
extern "C" void kernel_launch(void* const* d_in, const int* in_sizes, int n_in,
                              void* d_out, int out_size) {
    const float* X  = nullptr;   // 8388608
    const float* Wt = nullptr;   // 18874368
    const float* Bp = nullptr;   // 4096
    for (int i = 0; i < n_in; ++i) {
        if      (in_sizes[i] == B_ * CIN * HH * WW) X  = (const float*)d_in[i];
        else if (in_sizes[i] == S_ * KK * COUT)     Wt = (const float*)d_in[i];
        else if (in_sizes[i] == S_)                 Bp = (const float*)d_in[i];
    }

    cudaFuncSetAttribute(lc_kernel, cudaFuncAttributeMaxDynamicSharedMemorySize, SMEM_BYTES);

    transpose_kernel<<<CIN * HH, 256>>>(X);
    lc_kernel<<<S_, 256, SMEM_BYTES>>>(Wt, Bp, (float*)d_out);
}